// round 14
// baseline (speedup 1.0000x reference)
#include <cuda_runtime.h>
#include <cuda_bf16.h>
#include <cstdint>

// Shapes (fixed by the problem)
#define S_LEN 2048
#define DIM   5120
#define NH    40
#define DH    128
#define N3    15360   // 3*DIM

// ---------------------------------------------------------------------------
// Scratch (device globals: no allocation allowed in kernel_launch)
// ---------------------------------------------------------------------------
__device__ float g_qkv[(size_t)S_LEN * N3];        // 2048 x 15360 (QKV GEMM out)
__device__ __nv_bfloat16 g_Ah[(size_t)S_LEN * DIM];     // activations hi  [M][K]
__device__ __nv_bfloat16 g_Al[(size_t)S_LEN * DIM];     // activations lo
__device__ __nv_bfloat16 g_Wqkv_h[(size_t)N3 * DIM];    // w_qkv^T hi [N][K]
__device__ __nv_bfloat16 g_Wqkv_l[(size_t)N3 * DIM];
__device__ __nv_bfloat16 g_Wout_h[(size_t)DIM * DIM];   // w_out^T hi [N][K]
__device__ __nv_bfloat16 g_Wout_l[(size_t)DIM * DIM];
// bf16 hi/lo q/k (post norm+rope) and v for tensor-core attention, [s][DIM]
__device__ __nv_bfloat16 g_Qh[(size_t)S_LEN * DIM];
__device__ __nv_bfloat16 g_Ql[(size_t)S_LEN * DIM];
__device__ __nv_bfloat16 g_Kh[(size_t)S_LEN * DIM];
__device__ __nv_bfloat16 g_Kl[(size_t)S_LEN * DIM];
__device__ __nv_bfloat16 g_Vh[(size_t)S_LEN * DIM];
__device__ __nv_bfloat16 g_Vl[(size_t)S_LEN * DIM];

// ---------------------------------------------------------------------------
// Baseline-PTX helpers (sm_103 family target: no 'a' features)
// ---------------------------------------------------------------------------
__device__ __forceinline__ uint32_t smem_u32(const void* p) {
    uint32_t a;
    asm("{ .reg .u64 t; cvta.to.shared.u64 t, %1; cvt.u32.u64 %0, t; }"
        : "=r"(a) : "l"(p));
    return a;
}

#define CP_ASYNC16(dst, src) \
    asm volatile("cp.async.cg.shared.global [%0], [%1], 16;" \
        :: "r"(dst), "l"(src) : "memory")
#define CP_COMMIT() asm volatile("cp.async.commit_group;" ::: "memory")
#define CP_WAIT0()  asm volatile("cp.async.wait_group 0;" ::: "memory")
#define CP_WAIT1()  asm volatile("cp.async.wait_group 1;" ::: "memory")

#define LDMATRIX_X4(r0, r1, r2, r3, addr) \
    asm volatile("ldmatrix.sync.aligned.m8n8.x4.shared.b16 {%0,%1,%2,%3}, [%4];" \
        : "=r"(r0), "=r"(r1), "=r"(r2), "=r"(r3) : "r"(addr))
#define LDMATRIX_X4_T(r0, r1, r2, r3, addr) \
    asm volatile("ldmatrix.sync.aligned.m8n8.x4.trans.shared.b16 {%0,%1,%2,%3}, [%4];" \
        : "=r"(r0), "=r"(r1), "=r"(r2), "=r"(r3) : "r"(addr))

#define MMA_BF16(d, a, b) \
    asm volatile( \
        "mma.sync.aligned.m16n8k16.row.col.f32.bf16.bf16.f32 " \
        "{%0,%1,%2,%3}, {%4,%5,%6,%7}, {%8,%9}, {%0,%1,%2,%3};" \
        : "+f"((d)[0]), "+f"((d)[1]), "+f"((d)[2]), "+f"((d)[3]) \
        : "r"((a)[0]), "r"((a)[1]), "r"((a)[2]), "r"((a)[3]), \
          "r"((b)[0]), "r"((b)[1]))

__device__ __forceinline__ float fast_exp2(float x) {
    float y;
    asm("ex2.approx.f32 %0, %1;" : "=f"(y) : "f"(x));
    return y;
}

// fp32 pair -> packed bf16x2 hi + residual lo
__device__ __forceinline__ void split2(float a, float b, uint32_t& hi, uint32_t& lo) {
    __nv_bfloat16 ha = __float2bfloat16(a), hb = __float2bfloat16(b);
    __nv_bfloat162 h2(ha, hb);
    __nv_bfloat162 l2(__float2bfloat16(a - __bfloat162float(ha)),
                      __float2bfloat16(b - __bfloat162float(hb)));
    hi = *reinterpret_cast<uint32_t*>(&h2);
    lo = *reinterpret_cast<uint32_t*>(&l2);
}

// ---------------------------------------------------------------------------
// Prepass 1: elementwise fp32 -> (bf16 hi, bf16 lo), same layout.
// ---------------------------------------------------------------------------
__global__ __launch_bounds__(256)
void split_rows(const float* __restrict__ X, __nv_bfloat16* __restrict__ H,
                __nv_bfloat16* __restrict__ L)
{
    size_t i = ((size_t)blockIdx.x * 256 + threadIdx.x) * 4;
    float4 v = *reinterpret_cast<const float4*>(X + i);
    uint32_t h0, l0, h1, l1;
    split2(v.x, v.y, h0, l0);
    split2(v.z, v.w, h1, l1);
    uint32_t* Hp = reinterpret_cast<uint32_t*>(H + i);
    uint32_t* Lp = reinterpret_cast<uint32_t*>(L + i);
    Hp[0] = h0; Hp[1] = h1;
    Lp[0] = l0; Lp[1] = l1;
}

// ---------------------------------------------------------------------------
// Prepass 2: W[K][N] fp32 -> T_hi/T_lo [N][K] bf16 (transpose + split)
// ---------------------------------------------------------------------------
__global__ __launch_bounds__(256)
void transpose_split(const float* __restrict__ W, __nv_bfloat16* __restrict__ Th,
                     __nv_bfloat16* __restrict__ Tl, int K, int N)
{
    __shared__ float t[32][33];
    const int k0 = blockIdx.x * 32, n0 = blockIdx.y * 32;
    const int tx = threadIdx.x & 31, ty = threadIdx.x >> 5;
#pragma unroll
    for (int i = 0; i < 4; i++)
        t[ty + i * 8][tx] = W[(size_t)(k0 + ty + i * 8) * N + n0 + tx];
    __syncthreads();
#pragma unroll
    for (int i = 0; i < 4; i++) {
        const int n = n0 + ty + i * 8;
        const float v = t[tx][ty + i * 8];
        __nv_bfloat16 h = __float2bfloat16(v);
        __nv_bfloat16 l = __float2bfloat16(v - __bfloat162float(h));
        Th[(size_t)n * K + k0 + tx] = h;
        Tl[(size_t)n * K + k0 + tx] = l;
    }
}

// ---------------------------------------------------------------------------
// Tensor-core GEMM, bf16 hi/lo 3-term split, fp32 accum.
// ROUND 9: CTA tile 128x256, 8 warps, warp tile 64x64 (mf=4, 8 n-frags).
// Operand reuse per warp doubles: 16 LDSM feed 96 MMAs per k16
// (0.042 B/MAC vs 0.125 before) -> smem crossbar no longer the ceiling.
// 1 CTA/SM (launch_bounds(256,1), ~200 regs), double-buffered cp.async.
// ---------------------------------------------------------------------------
#define BK        32
#define SPITCHB   80                       // bytes per smem row (32 bf16 + pad)
#define A_TILEB   (128 * SPITCHB)          // 10240
#define B_TILEB   (256 * SPITCHB)          // 20480
#define OFF_AH    0
#define OFF_AL    (A_TILEB)
#define OFF_BH    (2 * A_TILEB)
#define OFF_BL    (2 * A_TILEB + B_TILEB)
#define STAGE_B   (2 * A_TILEB + 2 * B_TILEB)   // 61440
#define GEMM_SMEM (2 * STAGE_B)                 // 122880

__global__ __launch_bounds__(256, 1)
void gemm_tc(const __nv_bfloat16* __restrict__ Ah, const __nv_bfloat16* __restrict__ Al,
             const __nv_bfloat16* __restrict__ Bh, const __nv_bfloat16* __restrict__ Bl,
             const float* __restrict__ bias, float* __restrict__ C, int N)
{
    constexpr int K = DIM;
    constexpr int NCHUNK = K / BK;   // 160

    extern __shared__ char dsm[];
    const uint32_t sbase = smem_u32(dsm);

    const int tid = threadIdx.x;
    const int wid = tid >> 5, lane = tid & 31;
    const int warp_m = wid & 1;      // 2 x 64-row slices
    const int warp_n = wid >> 1;     // 4 x 64-col slices
    const int row0 = blockIdx.x * 128;
    const int col0 = blockIdx.y * 256;

    // K-phase stagger (kept from round 8; harmless, de-phases DRAM bursts)
    const int coff = ((blockIdx.y * gridDim.x + blockIdx.x) & 1) * (NCHUNK / 2);

    const __nv_bfloat16* gAh = Ah + (size_t)row0 * K;
    const __nv_bfloat16* gAl = Al + (size_t)row0 * K;
    const __nv_bfloat16* gBh = Bh + (size_t)col0 * K;
    const __nv_bfloat16* gBl = Bl + (size_t)col0 * K;

    auto chunk_koff = [&](int c) {
        int cc = c + coff;
        if (cc >= NCHUNK) cc -= NCHUNK;
        return cc * BK;
    };

    auto load_stage = [&](int stage, int koff) {
        const uint32_t sb = sbase + stage * STAGE_B;
        // A hi/lo: 128 rows x 4 granules = 512 each
#pragma unroll
        for (int i = 0; i < 2; ++i) {
            const int g = tid + i * 256;
            const int row = g >> 2, c16 = g & 3;
            const size_t goff = (size_t)row * K + koff + c16 * 8;
            const uint32_t doff = row * SPITCHB + c16 * 16;
            CP_ASYNC16(sb + OFF_AH + doff, gAh + goff);
            CP_ASYNC16(sb + OFF_AL + doff, gAl + goff);
        }
        // B hi/lo: 256 rows x 4 granules = 1024 each
#pragma unroll
        for (int i = 0; i < 4; ++i) {
            const int g = tid + i * 256;
            const int row = g >> 2, c16 = g & 3;
            const size_t goff = (size_t)row * K + koff + c16 * 8;
            const uint32_t doff = row * SPITCHB + c16 * 16;
            CP_ASYNC16(sb + OFF_BH + doff, gBh + goff);
            CP_ASYNC16(sb + OFF_BL + doff, gBl + goff);
        }
    };

    float acc[4][8][4];
#pragma unroll
    for (int i = 0; i < 4; i++)
#pragma unroll
        for (int j = 0; j < 8; j++)
#pragma unroll
            for (int v = 0; v < 4; v++) acc[i][j][v] = 0.f;

    load_stage(0, chunk_koff(0));
    CP_COMMIT();

    for (int c = 0; c < NCHUNK; ++c) {
        CP_WAIT0();
        __syncthreads();
        if (c + 1 < NCHUNK) {
            load_stage((c + 1) & 1, chunk_koff(c + 1));
            CP_COMMIT();
        }

        const uint32_t sb = sbase + (c & 1) * STAGE_B;
        const uint32_t sAh = sb + OFF_AH, sAl = sb + OFF_AL;
        const uint32_t sBh = sb + OFF_BH, sBl = sb + OFF_BL;

#pragma unroll
        for (int k16 = 0; k16 < 2; ++k16) {
            const uint32_t kb = k16 * 32;

            // B fragments for the whole 64-col slice (4 x n16, hi+lo)
            uint32_t b_h[4][4], b_l[4][4];
#pragma unroll
            for (int nq = 0; nq < 4; ++nq) {
                const uint32_t ro = (warp_n * 64 + nq * 16 + (lane & 7) + ((lane >> 4) << 3))
                                    * SPITCHB + (((lane >> 3) & 1) * 16) + kb;
                LDMATRIX_X4(b_h[nq][0], b_h[nq][1], b_h[nq][2], b_h[nq][3], sBh + ro);
                LDMATRIX_X4(b_l[nq][0], b_l[nq][1], b_l[nq][2], b_l[nq][3], sBl + ro);
            }

#pragma unroll
            for (int mf = 0; mf < 4; ++mf) {
                uint32_t aH[4], aL[4];
                const uint32_t aro = (warp_m * 64 + mf * 16 + (lane & 15)) * SPITCHB
                                     + ((lane >> 4) * 16) + kb;
                LDMATRIX_X4(aH[0], aH[1], aH[2], aH[3], sAh + aro);
                LDMATRIX_X4(aL[0], aL[1], aL[2], aL[3], sAl + aro);
                // pass hh over 8 n-frags
#pragma unroll
                for (int nq = 0; nq < 4; ++nq)
#pragma unroll
                    for (int half = 0; half < 2; ++half) {
                        uint32_t b2[2] = { b_h[nq][half * 2], b_h[nq][half * 2 + 1] };
                        MMA_BF16(acc[mf][nq * 2 + half], aH, b2);
                    }
                // pass hl
#pragma unroll
                for (int nq = 0; nq < 4; ++nq)
#pragma unroll
                    for (int half = 0; half < 2; ++half) {
                        uint32_t b2[2] = { b_l[nq][half * 2], b_l[nq][half * 2 + 1] };
                        MMA_BF16(acc[mf][nq * 2 + half], aH, b2);
                    }
                // pass lh
#pragma unroll
                for (int nq = 0; nq < 4; ++nq)
#pragma unroll
                    for (int half = 0; half < 2; ++half) {
                        uint32_t b2[2] = { b_h[nq][half * 2], b_h[nq][half * 2 + 1] };
                        MMA_BF16(acc[mf][nq * 2 + half], aL, b2);
                    }
            }
        }
    }

    // ---- Epilogue: 64x64 per warp, add bias, float2 stores ----
#pragma unroll
    for (int mf = 0; mf < 4; ++mf) {
        const int r0 = row0 + warp_m * 64 + mf * 16 + (lane >> 2);
#pragma unroll
        for (int nf = 0; nf < 8; ++nf) {
            const int col = col0 + warp_n * 64 + nf * 8 + (lane & 3) * 2;
            const float b0 = bias[col], b1 = bias[col + 1];
            float* p0 = C + (size_t)r0 * N + col;
            float* p1 = C + (size_t)(r0 + 8) * N + col;
            *reinterpret_cast<float2*>(p0) =
                make_float2(acc[mf][nf][0] + b0, acc[mf][nf][1] + b1);
            *reinterpret_cast<float2*>(p1) =
                make_float2(acc[mf][nf][2] + b0, acc[mf][nf][3] + b1);
        }
    }
}

// ---------------------------------------------------------------------------
// Fused RMSNorm(q,k) + RoPE + hi/lo split of q,k,v -> bf16 buffers [s][DIM].
// ---------------------------------------------------------------------------
__global__ __launch_bounds__(256)
void rmsnorm_rope_split(const float* __restrict__ qkv,
                        const float* __restrict__ cos_t,
                        const float* __restrict__ sin_t,
                        const float* __restrict__ wq,
                        const float* __restrict__ wk,
                        __nv_bfloat16* __restrict__ Qh, __nv_bfloat16* __restrict__ Ql,
                        __nv_bfloat16* __restrict__ Kh, __nv_bfloat16* __restrict__ Kl,
                        __nv_bfloat16* __restrict__ Vh, __nv_bfloat16* __restrict__ Vl)
{
    const int s = blockIdx.x;
    const float* q = qkv + (size_t)s * N3;
    const float* k = q + DIM;
    const float* v = k + DIM;

    float sq = 0.f, sk = 0.f;
    for (int i = threadIdx.x; i < DIM; i += blockDim.x) {
        float a = q[i]; sq += a * a;
        float b = k[i]; sk += b * b;
    }
#pragma unroll
    for (int o = 16; o; o >>= 1) {
        sq += __shfl_xor_sync(0xffffffffu, sq, o);
        sk += __shfl_xor_sync(0xffffffffu, sk, o);
    }
    __shared__ float red[2][32];
    const int wid = threadIdx.x >> 5, lid = threadIdx.x & 31;
    if (lid == 0) { red[0][wid] = sq; red[1][wid] = sk; }
    __syncthreads();
    if (threadIdx.x == 0) {
        float a = 0.f, b = 0.f;
        for (int i = 0; i < 8; i++) { a += red[0][i]; b += red[1][i]; }
        red[0][0] = a; red[1][0] = b;
    }
    __syncthreads();
    const float rq = rsqrtf(red[0][0] / (float)DIM + 1e-6f);
    const float rk = rsqrtf(red[1][0] / (float)DIM + 1e-6f);

    const size_t ob = (size_t)s * DIM;
    for (int p = threadIdx.x; p < DIM / 2; p += blockDim.x) {
        const int e = 2 * p, o = 2 * p + 1;
        const int ih = p & 63;
        const float ce = cos_t[s * DH + 2 * ih];
        const float so = sin_t[s * DH + 2 * ih + 1];

        float qe = q[e] * rq * wq[e], qo = q[o] * rq * wq[o];
        float ke = k[e] * rk * wk[e], ko = k[o] * rk * wk[o];
        uint32_t hi, lo;
        split2(qe * ce - qo * so, qe * so + qo * ce, hi, lo);
        *reinterpret_cast<uint32_t*>(Qh + ob + e) = hi;
        *reinterpret_cast<uint32_t*>(Ql + ob + e) = lo;
        split2(ke * ce - ko * so, ke * so + ko * ce, hi, lo);
        *reinterpret_cast<uint32_t*>(Kh + ob + e) = hi;
        *reinterpret_cast<uint32_t*>(Kl + ob + e) = lo;
        split2(v[e], v[o], hi, lo);
        *reinterpret_cast<uint32_t*>(Vh + ob + e) = hi;
        *reinterpret_cast<uint32_t*>(Vl + ob + e) = lo;
    }
}

// ---------------------------------------------------------------------------
// Tensor-core flash attention (mma.sync bf16 hi/lo, exp2-domain softmax).
// Unchanged from round 8 (KV-tile rotation kept).
// ---------------------------------------------------------------------------
#define A_BK     64
#define A_PITCHB 272
#define A_QBYTES (128 * A_PITCHB)
#define A_KTILE  (A_BK * A_PITCHB)
#define A_STAGE  (4 * A_KTILE)
#define ATTN_SMEM (2 * A_QBYTES + 2 * A_STAGE)

__global__ __launch_bounds__(256)
void attn_tc(const __nv_bfloat16* __restrict__ Qh, const __nv_bfloat16* __restrict__ Ql,
             const __nv_bfloat16* __restrict__ Kh, const __nv_bfloat16* __restrict__ Kl,
             const __nv_bfloat16* __restrict__ Vh, const __nv_bfloat16* __restrict__ Vl,
             __nv_bfloat16* __restrict__ Oh, __nv_bfloat16* __restrict__ Ol)
{
    extern __shared__ char dsm[];
    const uint32_t base = smem_u32(dsm);
    const uint32_t sQh = base, sQl = base + A_QBYTES;
    const uint32_t stage0 = base + 2 * A_QBYTES;

    const int qb = blockIdx.x;
    const int h  = blockIdx.y;
    const int tid = threadIdx.x;
    const int warp = tid >> 5, lane = tid & 31;

    constexpr int NT = S_LEN / A_BK;              // 32
    const int toff = ((qb + h) & 3) * (NT / 4);   // 0, 8, 16, 24

    const __nv_bfloat16* kvsrc[4] = { Kh, Kl, Vh, Vl };

    {
        const size_t qoff = (size_t)(qb * 128) * DIM + h * DH;
#pragma unroll
        for (int g = 0; g < 8; ++g) {
            const int idx = tid + g * 256;
            const int row = idx >> 4, c = idx & 15;
            const size_t so = qoff + (size_t)row * DIM + c * 8;
            CP_ASYNC16(sQh + row * A_PITCHB + c * 16, Qh + so);
            CP_ASYNC16(sQl + row * A_PITCHB + c * 16, Ql + so);
        }
    }
    auto ktile = [&](int i) {
        int t = i + toff;
        return t >= NT ? t - NT : t;
    };
    auto load_kv = [&](uint32_t st, int kt) {
        const size_t koff = (size_t)(kt * A_BK) * DIM + h * DH;
#pragma unroll
        for (int g = 0; g < 16; ++g) {
            const int t = g >> 2;
            const int idx = tid + (g & 3) * 256;
            const int row = idx >> 4, c = idx & 15;
            CP_ASYNC16(st + t * A_KTILE + row * A_PITCHB + c * 16,
                       kvsrc[t] + koff + (size_t)row * DIM + c * 8);
        }
    };

    load_kv(stage0, ktile(0));
    CP_COMMIT();
    load_kv(stage0 + A_STAGE, ktile(1));
    CP_COMMIT();

    float O[16][4];
#pragma unroll
    for (int i = 0; i < 16; i++)
#pragma unroll
        for (int j = 0; j < 4; j++) O[i][j] = 0.f;
    float m_run[2] = { -1e30f, -1e30f };
    float l_run[2] = { 0.f, 0.f };
    const float scale2 = 0.08838834764831845f * 1.4426950408889634f;

    for (int kt = 0; kt < NT; ++kt) {
        if (kt == NT - 1) { CP_WAIT0(); } else { CP_WAIT1(); }
        __syncthreads();

        const uint32_t st = stage0 + (kt & 1) * A_STAGE;
        const uint32_t sKh = st, sKl = st + A_KTILE;
        const uint32_t sVh = st + 2 * A_KTILE, sVl = st + 3 * A_KTILE;

        // ---- S = Q K^T (16 x 64 per warp), 3-term split ----
        float sacc[8][4];
#pragma unroll
        for (int i = 0; i < 8; i++)
#pragma unroll
            for (int j = 0; j < 4; j++) sacc[i][j] = 0.f;

#pragma unroll
        for (int ks = 0; ks < 8; ++ks) {
            const uint32_t kb = ks * 32;
            uint32_t aH[4], aL[4];
            const uint32_t aro = (warp * 16 + (lane & 15)) * A_PITCHB
                                 + ((lane >> 4) * 16) + kb;
            LDMATRIX_X4(aH[0], aH[1], aH[2], aH[3], sQh + aro);
            LDMATRIX_X4(aL[0], aL[1], aL[2], aL[3], sQl + aro);
            uint32_t bH[4][4], bL[4][4];
#pragma unroll
            for (int nb = 0; nb < 4; ++nb) {
                const uint32_t bro = (nb * 16 + (lane & 7) + ((lane >> 4) << 3))
                                     * A_PITCHB + (((lane >> 3) & 1) * 16) + kb;
                LDMATRIX_X4(bH[nb][0], bH[nb][1], bH[nb][2], bH[nb][3], sKh + bro);
                LDMATRIX_X4(bL[nb][0], bL[nb][1], bL[nb][2], bL[nb][3], sKl + bro);
            }
#pragma unroll
            for (int nb = 0; nb < 4; ++nb)
#pragma unroll
                for (int half = 0; half < 2; ++half) {
                    uint32_t b2[2] = { bH[nb][half * 2], bH[nb][half * 2 + 1] };
                    MMA_BF16(sacc[nb * 2 + half], aH, b2);
                }
#pragma unroll
            for (int nb = 0; nb < 4; ++nb)
#pragma unroll
                for (int half = 0; half < 2; ++half) {
                    uint32_t b2[2] = { bL[nb][half * 2], bL[nb][half * 2 + 1] };
                    MMA_BF16(sacc[nb * 2 + half], aH, b2);
                }
#pragma unroll
            for (int nb = 0; nb < 4; ++nb)
#pragma unroll
                for (int half = 0; half < 2; ++half) {
                    uint32_t b2[2] = { bH[nb][half * 2], bH[nb][half * 2 + 1] };
                    MMA_BF16(sacc[nb * 2 + half], aL, b2);
                }
        }

        // ---- online softmax in log2 domain ----
        float mt0 = -1e30f, mt1 = -1e30f;
#pragma unroll
        for (int f = 0; f < 8; ++f) {
            sacc[f][0] *= scale2; sacc[f][1] *= scale2;
            sacc[f][2] *= scale2; sacc[f][3] *= scale2;
            mt0 = fmaxf(mt0, fmaxf(sacc[f][0], sacc[f][1]));
            mt1 = fmaxf(mt1, fmaxf(sacc[f][2], sacc[f][3]));
        }
        mt0 = fmaxf(mt0, __shfl_xor_sync(0xffffffffu, mt0, 1));
        mt0 = fmaxf(mt0, __shfl_xor_sync(0xffffffffu, mt0, 2));
        mt1 = fmaxf(mt1, __shfl_xor_sync(0xffffffffu, mt1, 1));
        mt1 = fmaxf(mt1, __shfl_xor_sync(0xffffffffu, mt1, 2));
        const float mn0 = fmaxf(m_run[0], mt0), mn1 = fmaxf(m_run[1], mt1);
        const float al0 = fast_exp2(m_run[0] - mn0), al1 = fast_exp2(m_run[1] - mn1);
        m_run[0] = mn0; m_run[1] = mn1;

        float ls0 = 0.f, ls1 = 0.f;
#pragma unroll
        for (int f = 0; f < 8; ++f) {
            sacc[f][0] = fast_exp2(sacc[f][0] - mn0);
            sacc[f][1] = fast_exp2(sacc[f][1] - mn0);
            sacc[f][2] = fast_exp2(sacc[f][2] - mn1);
            sacc[f][3] = fast_exp2(sacc[f][3] - mn1);
            ls0 += sacc[f][0] + sacc[f][1];
            ls1 += sacc[f][2] + sacc[f][3];
        }
        ls0 += __shfl_xor_sync(0xffffffffu, ls0, 1);
        ls0 += __shfl_xor_sync(0xffffffffu, ls0, 2);
        ls1 += __shfl_xor_sync(0xffffffffu, ls1, 1);
        ls1 += __shfl_xor_sync(0xffffffffu, ls1, 2);
        l_run[0] = l_run[0] * al0 + ls0;
        l_run[1] = l_run[1] * al1 + ls1;

#pragma unroll
        for (int i = 0; i < 16; i++) {
            O[i][0] *= al0; O[i][1] *= al0;
            O[i][2] *= al1; O[i][3] *= al1;
        }

        // P accum-frags -> A-operand frags (hi/lo)
        uint32_t pH[4][4], pL[4][4];
#pragma unroll
        for (int j = 0; j < 4; ++j) {
            split2(sacc[2 * j][0],     sacc[2 * j][1],     pH[j][0], pL[j][0]);
            split2(sacc[2 * j][2],     sacc[2 * j][3],     pH[j][1], pL[j][1]);
            split2(sacc[2 * j + 1][0], sacc[2 * j + 1][1], pH[j][2], pL[j][2]);
            split2(sacc[2 * j + 1][2], sacc[2 * j + 1][3], pH[j][3], pL[j][3]);
        }

        // ---- O += P V (V via ldmatrix.trans), 3-term split ----
#pragma unroll
        for (int ks = 0; ks < 4; ++ks) {
            const uint32_t krow = ks * 16 + (lane & 7) + (((lane >> 3) & 1) * 8);
            uint32_t bH[8][4], bL[8][4];
#pragma unroll
            for (int nb = 0; nb < 8; ++nb) {
                const uint32_t ro = krow * A_PITCHB + nb * 32 + ((lane >> 4) * 16);
                LDMATRIX_X4_T(bH[nb][0], bH[nb][1], bH[nb][2], bH[nb][3], sVh + ro);
                LDMATRIX_X4_T(bL[nb][0], bL[nb][1], bL[nb][2], bL[nb][3], sVl + ro);
            }
#pragma unroll
            for (int nb = 0; nb < 8; ++nb)
#pragma unroll
                for (int half = 0; half < 2; ++half) {
                    uint32_t b2[2] = { bH[nb][half * 2], bH[nb][half * 2 + 1] };
                    MMA_BF16(O[nb * 2 + half], pH[ks], b2);
                }
#pragma unroll
            for (int nb = 0; nb < 8; ++nb)
#pragma unroll
                for (int half = 0; half < 2; ++half) {
                    uint32_t b2[2] = { bL[nb][half * 2], bL[nb][half * 2 + 1] };
                    MMA_BF16(O[nb * 2 + half], pH[ks], b2);
                }
#pragma unroll
            for (int nb = 0; nb < 8; ++nb)
#pragma unroll
                for (int half = 0; half < 2; ++half) {
                    uint32_t b2[2] = { bH[nb][half * 2], bH[nb][half * 2 + 1] };
                    MMA_BF16(O[nb * 2 + half], pL[ks], b2);
                }
        }

        __syncthreads();
        if (kt + 2 < NT) {
            load_kv(stage0 + (kt & 1) * A_STAGE, ktile(kt + 2));
            CP_COMMIT();
        }
    }

    // ---- epilogue: write bf16 hi/lo operands for out-proj GEMM ----
    const float inv0 = 1.f / l_run[0], inv1 = 1.f / l_run[1];
    const int s0 = qb * 128 + warp * 16 + (lane >> 2);
#pragma unroll
    for (int nf = 0; nf < 16; ++nf) {
        const int col = h * DH + nf * 8 + (lane & 3) * 2;
        uint32_t hi, lo;
        split2(O[nf][0] * inv0, O[nf][1] * inv0, hi, lo);
        *reinterpret_cast<uint32_t*>(Oh + (size_t)s0 * DIM + col) = hi;
        *reinterpret_cast<uint32_t*>(Ol + (size_t)s0 * DIM + col) = lo;
        split2(O[nf][2] * inv1, O[nf][3] * inv1, hi, lo);
        *reinterpret_cast<uint32_t*>(Oh + (size_t)(s0 + 8) * DIM + col) = hi;
        *reinterpret_cast<uint32_t*>(Ol + (size_t)(s0 + 8) * DIM + col) = lo;
    }
}

// ---------------------------------------------------------------------------
// Launch
// ---------------------------------------------------------------------------
extern "C" void kernel_launch(void* const* d_in, const int* in_sizes, int n_in,
                              void* d_out, int out_size)
{
    const float* hidden = (const float*)d_in[0];
    const float* cos_t  = (const float*)d_in[1];
    const float* sin_t  = (const float*)d_in[2];
    const float* w_qkv  = (const float*)d_in[3];
    const float* b_qkv  = (const float*)d_in[4];
    const float* w_qn   = (const float*)d_in[5];
    const float* w_kn   = (const float*)d_in[6];
    const float* w_out  = (const float*)d_in[7];
    const float* b_out  = (const float*)d_in[8];
    float* out = (float*)d_out;

    float* qkv;
    __nv_bfloat16 *Ah, *Al, *Wqh, *Wql, *Woh, *Wol, *Qh, *Ql, *Kh, *Kl, *Vh, *Vl;
    cudaGetSymbolAddress((void**)&qkv, g_qkv);
    cudaGetSymbolAddress((void**)&Ah, g_Ah);
    cudaGetSymbolAddress((void**)&Al, g_Al);
    cudaGetSymbolAddress((void**)&Wqh, g_Wqkv_h);
    cudaGetSymbolAddress((void**)&Wql, g_Wqkv_l);
    cudaGetSymbolAddress((void**)&Woh, g_Wout_h);
    cudaGetSymbolAddress((void**)&Wol, g_Wout_l);
    cudaGetSymbolAddress((void**)&Qh, g_Qh);
    cudaGetSymbolAddress((void**)&Ql, g_Ql);
    cudaGetSymbolAddress((void**)&Kh, g_Kh);
    cudaGetSymbolAddress((void**)&Kl, g_Kl);
    cudaGetSymbolAddress((void**)&Vh, g_Vh);
    cudaGetSymbolAddress((void**)&Vl, g_Vl);

    cudaFuncSetAttribute(gemm_tc, cudaFuncAttributeMaxDynamicSharedMemorySize,
                         GEMM_SMEM);
    cudaFuncSetAttribute(attn_tc, cudaFuncAttributeMaxDynamicSharedMemorySize,
                         ATTN_SMEM);

    // Prepass: weight transpose+split, activation split
    transpose_split<<<dim3(DIM / 32, N3 / 32), 256>>>(w_qkv, Wqh, Wql, DIM, N3);
    transpose_split<<<dim3(DIM / 32, DIM / 32), 256>>>(w_out, Woh, Wol, DIM, DIM);
    split_rows<<<(S_LEN * DIM) / 1024, 256>>>(hidden, Ah, Al);

    // 1) QKV = X @ Wqkv + b (tensor cores, 128x256 tiles)
    gemm_tc<<<dim3(S_LEN / 128, N3 / 256), 256, GEMM_SMEM>>>(
        Ah, Al, Wqh, Wql, b_qkv, qkv, N3);

    // 2) RMSNorm + RoPE + split q,k,v to bf16 hi/lo
    rmsnorm_rope_split<<<S_LEN, 256>>>(qkv, cos_t, sin_t, w_qn, w_kn,
                                       Qh, Ql, Kh, Kl, Vh, Vl);

    // 3) Tensor-core flash attention (emits bf16 hi/lo directly into Ah/Al)
    attn_tc<<<dim3(S_LEN / 128, NH), 256, ATTN_SMEM>>>(Qh, Ql, Kh, Kl, Vh, Vl, Ah, Al);

    // 4) out = attn_out @ Wout + b (tensor cores, 128x256 tiles)
    gemm_tc<<<dim3(S_LEN / 128, DIM / 256), 256, GEMM_SMEM>>>(
        Ah, Al, Woh, Wol, b_out, out, DIM);
}

// round 15
// speedup vs baseline: 1.4325x; 1.4325x over previous
#include <cuda_runtime.h>
#include <cuda_bf16.h>
#include <cstdint>

// Shapes (fixed by the problem)
#define S_LEN 2048
#define DIM   5120
#define NH    40
#define DH    128
#define N3    15360   // 3*DIM

// ---------------------------------------------------------------------------
// Scratch (device globals)
// ---------------------------------------------------------------------------
__device__ float g_qkv[(size_t)S_LEN * N3];          // QKV GEMM out; later attn out (first S*DIM)
__device__ float g_At[(size_t)S_LEN * DIM];          // tf32 frag-major activations
__device__ float g_Wqkv_t[(size_t)N3 * DIM];         // tf32 frag-major w_qkv^T
__device__ float g_Wout_t[(size_t)DIM * DIM];        // tf32 frag-major w_out^T
// bf16 hi/lo q/k/v for tensor-core attention, [s][DIM]
__device__ __nv_bfloat16 g_Qh[(size_t)S_LEN * DIM];
__device__ __nv_bfloat16 g_Ql[(size_t)S_LEN * DIM];
__device__ __nv_bfloat16 g_Kh[(size_t)S_LEN * DIM];
__device__ __nv_bfloat16 g_Kl[(size_t)S_LEN * DIM];
__device__ __nv_bfloat16 g_Vh[(size_t)S_LEN * DIM];
__device__ __nv_bfloat16 g_Vl[(size_t)S_LEN * DIM];

// ---------------------------------------------------------------------------
// Baseline-PTX helpers
// ---------------------------------------------------------------------------
__device__ __forceinline__ uint32_t smem_u32(const void* p) {
    uint32_t a;
    asm("{ .reg .u64 t; cvta.to.shared.u64 t, %1; cvt.u32.u64 %0, t; }"
        : "=r"(a) : "l"(p));
    return a;
}

#define CP_ASYNC16(dst, src) \
    asm volatile("cp.async.cg.shared.global [%0], [%1], 16;" \
        :: "r"(dst), "l"(src) : "memory")
#define CP_COMMIT() asm volatile("cp.async.commit_group;" ::: "memory")
#define CP_WAIT0()  asm volatile("cp.async.wait_group 0;" ::: "memory")
#define CP_WAIT1()  asm volatile("cp.async.wait_group 1;" ::: "memory")

#define LDMATRIX_X4(r0, r1, r2, r3, addr) \
    asm volatile("ldmatrix.sync.aligned.m8n8.x4.shared.b16 {%0,%1,%2,%3}, [%4];" \
        : "=r"(r0), "=r"(r1), "=r"(r2), "=r"(r3) : "r"(addr))
#define LDMATRIX_X4_T(r0, r1, r2, r3, addr) \
    asm volatile("ldmatrix.sync.aligned.m8n8.x4.trans.shared.b16 {%0,%1,%2,%3}, [%4];" \
        : "=r"(r0), "=r"(r1), "=r"(r2), "=r"(r3) : "r"(addr))

#define LDS128U(r0, r1, r2, r3, addr) \
    asm volatile("ld.shared.v4.b32 {%0,%1,%2,%3}, [%4];" \
        : "=r"(r0), "=r"(r1), "=r"(r2), "=r"(r3) : "r"(addr))

#define MMA_BF16(d, a, b) \
    asm volatile( \
        "mma.sync.aligned.m16n8k16.row.col.f32.bf16.bf16.f32 " \
        "{%0,%1,%2,%3}, {%4,%5,%6,%7}, {%8,%9}, {%0,%1,%2,%3};" \
        : "+f"((d)[0]), "+f"((d)[1]), "+f"((d)[2]), "+f"((d)[3]) \
        : "r"((a)[0]), "r"((a)[1]), "r"((a)[2]), "r"((a)[3]), \
          "r"((b)[0]), "r"((b)[1]))

#define MMA_TF32(d, a, b0v, b1v) \
    asm volatile( \
        "mma.sync.aligned.m16n8k8.row.col.f32.tf32.tf32.f32 " \
        "{%0,%1,%2,%3}, {%4,%5,%6,%7}, {%8,%9}, {%0,%1,%2,%3};" \
        : "+f"((d)[0]), "+f"((d)[1]), "+f"((d)[2]), "+f"((d)[3]) \
        : "r"((a)[0]), "r"((a)[1]), "r"((a)[2]), "r"((a)[3]), \
          "r"(b0v), "r"(b1v))

__device__ __forceinline__ uint32_t f2tf32(float x) {
    uint32_t y;
    asm("cvt.rna.tf32.f32 %0, %1;" : "=r"(y) : "f"(x));
    return y;
}

__device__ __forceinline__ float fast_exp2(float x) {
    float y;
    asm("ex2.approx.f32 %0, %1;" : "=f"(y) : "f"(x));
    return y;
}

// fp32 pair -> packed bf16x2 hi + residual lo (attention path)
__device__ __forceinline__ void split2(float a, float b, uint32_t& hi, uint32_t& lo) {
    __nv_bfloat16 ha = __float2bfloat16(a), hb = __float2bfloat16(b);
    __nv_bfloat162 h2(ha, hb);
    __nv_bfloat162 l2(__float2bfloat16(a - __bfloat162float(ha)),
                      __float2bfloat16(b - __bfloat162float(hb)));
    hi = *reinterpret_cast<uint32_t*>(&h2);
    lo = *reinterpret_cast<uint32_t*>(&l2);
}

// ---------------------------------------------------------------------------
// Prepass A: X [M][K] fp32 -> frag-major tf32 blocks (m16 x k8, 512 B each).
// Block id = m_blk*(K/8) + k_blk. Within block, lane l, regs r0..r3 =
// mma m16n8k8 A-fragment order: (row+{0,8}, col+{0,4}).
// One thread per output float4 (= one lane of one block).
// ---------------------------------------------------------------------------
__global__ __launch_bounds__(256)
void a_to_tf32_frag(const float* __restrict__ X, float* __restrict__ At, int K)
{
    const size_t gid = (size_t)blockIdx.x * 256 + threadIdx.x;
    const int lane = (int)(gid & 31);
    const size_t blk = gid >> 5;
    const int kb = (int)(blk % (K / 8));
    const int mb = (int)(blk / (K / 8));
    const int row = mb * 16 + (lane >> 2);
    const int col = kb * 8 + (lane & 3);
    uint4 o;
    o.x = f2tf32(X[(size_t)row * K + col]);
    o.y = f2tf32(X[(size_t)(row + 8) * K + col]);
    o.z = f2tf32(X[(size_t)row * K + col + 4]);
    o.w = f2tf32(X[(size_t)(row + 8) * K + col + 4]);
    reinterpret_cast<uint4*>(At)[gid] = o;
}

// ---------------------------------------------------------------------------
// Prepass B: W [K][N] fp32 -> frag-major tf32 blocks (n8 x k16, 512 B each).
// Block id = n_blk*(K/16) + k_blk. Lane regs = {b0_s0, b1_s0, b0_s1, b1_s1}
// of mma m16n8k8 B-fragments for the two k8 steps: k offsets {0,4,8,12},
// n = n_blk*8 + (lane>>2), k = k_blk*16 + (lane&3) + off.
// Grid: x = n_blk (fast; keeps 16 k-rows hot in L2), y = k_blk group.
// ---------------------------------------------------------------------------
__global__ __launch_bounds__(256)
void w_to_tf32_frag(const float* __restrict__ W, float* __restrict__ Bt,
                    int K, int N)
{
    // 8 blocks (each 32 lanes) per 256-thread CTA
    const int lane = threadIdx.x & 31;
    const int sub  = threadIdx.x >> 5;                // 0..7
    const int nb   = blockIdx.x * 8 + sub;            // n_blk
    const int kb   = blockIdx.y;                      // k_blk
    const int n = nb * 8 + (lane >> 2);
    const int k = kb * 16 + (lane & 3);
    uint4 o;
    o.x = f2tf32(W[(size_t)k * N + n]);
    o.y = f2tf32(W[(size_t)(k + 4) * N + n]);
    o.z = f2tf32(W[(size_t)(k + 8) * N + n]);
    o.w = f2tf32(W[(size_t)(k + 12) * N + n]);
    const size_t blk = (size_t)nb * (K / 16) + kb;
    reinterpret_cast<uint4*>(Bt)[blk * 32 + lane] = o;
}

// ---------------------------------------------------------------------------
// tf32 GEMM: C[M,N] = A@B + bias. A,B in frag-major tf32 layouts above.
// CTA 128x128, 8 warps (warp tile 32x64), BK=32, cp.async double buffer,
// 2 CTAs/SM, K-phase stagger. Fragments via single conflict-free LDS.128.
// ---------------------------------------------------------------------------
#define BK        32
#define A_STG     16384                    // 8 mb * 4 kb8 * 512
#define B_STG     16384                    // 16 nb * 2 kb16 * 512
#define STAGE_B   (A_STG + B_STG)          // 32768
#define GEMM_SMEM (2 * STAGE_B)            // 65536

__global__ __launch_bounds__(256, 2)
void gemm_tf32(const float* __restrict__ At, const float* __restrict__ Bt,
               const float* __restrict__ bias, float* __restrict__ C, int N)
{
    constexpr int K = DIM;
    constexpr int NCHUNK = K / BK;   // 160
    const int KB8 = K / 8, KB16 = K / 16;

    extern __shared__ char dsm[];
    const uint32_t sbase = smem_u32(dsm);

    const int tid = threadIdx.x;
    const int wid = tid >> 5, lane = tid & 31;
    const int warp_m = wid & 3;      // 4 x 32-row slices
    const int warp_n = wid >> 2;     // 2 x 64-col slices
    const int mb0 = blockIdx.x * 8;  // first m16-block of CTA
    const int nb0 = blockIdx.y * 16; // first n8-block of CTA

    const int coff = ((blockIdx.y * gridDim.x + blockIdx.x) & 1) * (NCHUNK / 2);
    auto chunk_koff = [&](int c) {
        int cc = c + coff;
        if (cc >= NCHUNK) cc -= NCHUNK;
        return cc * BK;
    };

    auto load_stage = [&](int stage, int koff) {
        const uint32_t sb = sbase + stage * STAGE_B;
        const int kb8_0 = koff / 8, kb16_0 = koff / 16;
        // A: 32 blocks (8 mb x 4 kb8), 1024 granules, 4/thread
#pragma unroll
        for (int i = 0; i < 4; ++i) {
            const int g = tid + i * 256;
            const int ab = g >> 5, l = g & 31;
            const int mb = ab >> 2, kb = ab & 3;
            const float* src = At + ((size_t)(mb0 + mb) * KB8 + kb8_0 + kb) * 128 + l * 4;
            CP_ASYNC16(sb + ab * 512 + l * 16, src);
        }
        // B: 32 blocks (16 nb x 2 kb16), 1024 granules, 4/thread
#pragma unroll
        for (int i = 0; i < 4; ++i) {
            const int g = tid + i * 256;
            const int bb = g >> 5, l = g & 31;
            const int nb = bb >> 1, kb = bb & 1;
            const float* src = Bt + ((size_t)(nb0 + nb) * KB16 + kb16_0 + kb) * 128 + l * 4;
            CP_ASYNC16(sb + A_STG + bb * 512 + l * 16, src);
        }
    };

    float acc[2][8][4];
#pragma unroll
    for (int i = 0; i < 2; i++)
#pragma unroll
        for (int j = 0; j < 8; j++)
#pragma unroll
            for (int v = 0; v < 4; v++) acc[i][j][v] = 0.f;

    load_stage(0, chunk_koff(0));
    CP_COMMIT();

    for (int c = 0; c < NCHUNK; ++c) {
        CP_WAIT0();
        __syncthreads();
        if (c + 1 < NCHUNK) {
            load_stage((c + 1) & 1, chunk_koff(c + 1));
            CP_COMMIT();
        }

        const uint32_t sb = sbase + (c & 1) * STAGE_B;
        const uint32_t sA = sb, sB = sb + A_STG;

#pragma unroll
        for (int q = 0; q < 2; ++q) {           // two k16 groups in chunk
            // B fragments: 8 n8-blocks x 4 regs ({b0s0,b1s0,b0s1,b1s1})
            uint32_t bf[8][4];
#pragma unroll
            for (int nf = 0; nf < 8; ++nf) {
                const uint32_t ro = (uint32_t)(((warp_n * 8 + nf) * 2 + q) * 512 + lane * 16);
                LDS128U(bf[nf][0], bf[nf][1], bf[nf][2], bf[nf][3], sB + ro);
            }
#pragma unroll
            for (int mf = 0; mf < 2; ++mf) {
                uint32_t af[2][4];              // two k8 steps
#pragma unroll
                for (int s = 0; s < 2; ++s) {
                    const uint32_t ro = (uint32_t)(((warp_m * 2 + mf) * 4 + q * 2 + s) * 512
                                                   + lane * 16);
                    LDS128U(af[s][0], af[s][1], af[s][2], af[s][3], sA + ro);
                }
                // k8 step 0 over all 8 n-frags, then step 1
#pragma unroll
                for (int nf = 0; nf < 8; ++nf)
                    MMA_TF32(acc[mf][nf], af[0], bf[nf][0], bf[nf][1]);
#pragma unroll
                for (int nf = 0; nf < 8; ++nf)
                    MMA_TF32(acc[mf][nf], af[1], bf[nf][2], bf[nf][3]);
            }
        }
    }

    // ---- Epilogue (same d-frag mapping as before) ----
#pragma unroll
    for (int mf = 0; mf < 2; ++mf) {
        const int r0 = (mb0 + warp_m * 2 + mf) * 16 + (lane >> 2);
#pragma unroll
        for (int nf = 0; nf < 8; ++nf) {
            const int col = (nb0 + warp_n * 8 + nf) * 8 + (lane & 3) * 2;
            const float b0 = bias[col], b1 = bias[col + 1];
            float* p0 = C + (size_t)r0 * N + col;
            float* p1 = C + (size_t)(r0 + 8) * N + col;
            *reinterpret_cast<float2*>(p0) =
                make_float2(acc[mf][nf][0] + b0, acc[mf][nf][1] + b1);
            *reinterpret_cast<float2*>(p1) =
                make_float2(acc[mf][nf][2] + b0, acc[mf][nf][3] + b1);
        }
    }
}

// ---------------------------------------------------------------------------
// Fused RMSNorm(q,k) + RoPE + hi/lo split of q,k,v -> bf16 buffers [s][DIM].
// ---------------------------------------------------------------------------
__global__ __launch_bounds__(256)
void rmsnorm_rope_split(const float* __restrict__ qkv,
                        const float* __restrict__ cos_t,
                        const float* __restrict__ sin_t,
                        const float* __restrict__ wq,
                        const float* __restrict__ wk,
                        __nv_bfloat16* __restrict__ Qh, __nv_bfloat16* __restrict__ Ql,
                        __nv_bfloat16* __restrict__ Kh, __nv_bfloat16* __restrict__ Kl,
                        __nv_bfloat16* __restrict__ Vh, __nv_bfloat16* __restrict__ Vl)
{
    const int s = blockIdx.x;
    const float* q = qkv + (size_t)s * N3;
    const float* k = q + DIM;
    const float* v = k + DIM;

    float sq = 0.f, sk = 0.f;
    for (int i = threadIdx.x; i < DIM; i += blockDim.x) {
        float a = q[i]; sq += a * a;
        float b = k[i]; sk += b * b;
    }
#pragma unroll
    for (int o = 16; o; o >>= 1) {
        sq += __shfl_xor_sync(0xffffffffu, sq, o);
        sk += __shfl_xor_sync(0xffffffffu, sk, o);
    }
    __shared__ float red[2][32];
    const int wid = threadIdx.x >> 5, lid = threadIdx.x & 31;
    if (lid == 0) { red[0][wid] = sq; red[1][wid] = sk; }
    __syncthreads();
    if (threadIdx.x == 0) {
        float a = 0.f, b = 0.f;
        for (int i = 0; i < 8; i++) { a += red[0][i]; b += red[1][i]; }
        red[0][0] = a; red[1][0] = b;
    }
    __syncthreads();
    const float rq = rsqrtf(red[0][0] / (float)DIM + 1e-6f);
    const float rk = rsqrtf(red[1][0] / (float)DIM + 1e-6f);

    const size_t ob = (size_t)s * DIM;
    for (int p = threadIdx.x; p < DIM / 2; p += blockDim.x) {
        const int e = 2 * p, o = 2 * p + 1;
        const int ih = p & 63;
        const float ce = cos_t[s * DH + 2 * ih];
        const float so = sin_t[s * DH + 2 * ih + 1];

        float qe = q[e] * rq * wq[e], qo = q[o] * rq * wq[o];
        float ke = k[e] * rk * wk[e], ko = k[o] * rk * wk[o];
        uint32_t hi, lo;
        split2(qe * ce - qo * so, qe * so + qo * ce, hi, lo);
        *reinterpret_cast<uint32_t*>(Qh + ob + e) = hi;
        *reinterpret_cast<uint32_t*>(Ql + ob + e) = lo;
        split2(ke * ce - ko * so, ke * so + ko * ce, hi, lo);
        *reinterpret_cast<uint32_t*>(Kh + ob + e) = hi;
        *reinterpret_cast<uint32_t*>(Kl + ob + e) = lo;
        split2(v[e], v[o], hi, lo);
        *reinterpret_cast<uint32_t*>(Vh + ob + e) = hi;
        *reinterpret_cast<uint32_t*>(Vl + ob + e) = lo;
    }
}

// ---------------------------------------------------------------------------
// Tensor-core flash attention (mma.sync bf16 hi/lo, exp2-domain softmax).
// Round-8 best config; epilogue writes fp32 (consumed by tf32 frag prepass).
// ---------------------------------------------------------------------------
#define A_BK     64
#define A_PITCHB 272
#define A_QBYTES (128 * A_PITCHB)
#define A_KTILE  (A_BK * A_PITCHB)
#define A_STAGE  (4 * A_KTILE)
#define ATTN_SMEM (2 * A_QBYTES + 2 * A_STAGE)

__global__ __launch_bounds__(256)
void attn_tc(const __nv_bfloat16* __restrict__ Qh, const __nv_bfloat16* __restrict__ Ql,
             const __nv_bfloat16* __restrict__ Kh, const __nv_bfloat16* __restrict__ Kl,
             const __nv_bfloat16* __restrict__ Vh, const __nv_bfloat16* __restrict__ Vl,
             float* __restrict__ out)
{
    extern __shared__ char dsm[];
    const uint32_t base = smem_u32(dsm);
    const uint32_t sQh = base, sQl = base + A_QBYTES;
    const uint32_t stage0 = base + 2 * A_QBYTES;

    const int qb = blockIdx.x;
    const int h  = blockIdx.y;
    const int tid = threadIdx.x;
    const int warp = tid >> 5, lane = tid & 31;

    constexpr int NT = S_LEN / A_BK;              // 32
    const int toff = ((qb + h) & 3) * (NT / 4);

    const __nv_bfloat16* kvsrc[4] = { Kh, Kl, Vh, Vl };

    {
        const size_t qoff = (size_t)(qb * 128) * DIM + h * DH;
#pragma unroll
        for (int g = 0; g < 8; ++g) {
            const int idx = tid + g * 256;
            const int row = idx >> 4, c = idx & 15;
            const size_t so = qoff + (size_t)row * DIM + c * 8;
            CP_ASYNC16(sQh + row * A_PITCHB + c * 16, Qh + so);
            CP_ASYNC16(sQl + row * A_PITCHB + c * 16, Ql + so);
        }
    }
    auto ktile = [&](int i) {
        int t = i + toff;
        return t >= NT ? t - NT : t;
    };
    auto load_kv = [&](uint32_t st, int kt) {
        const size_t koff = (size_t)(kt * A_BK) * DIM + h * DH;
#pragma unroll
        for (int g = 0; g < 16; ++g) {
            const int t = g >> 2;
            const int idx = tid + (g & 3) * 256;
            const int row = idx >> 4, c = idx & 15;
            CP_ASYNC16(st + t * A_KTILE + row * A_PITCHB + c * 16,
                       kvsrc[t] + koff + (size_t)row * DIM + c * 8);
        }
    };

    load_kv(stage0, ktile(0));
    CP_COMMIT();
    load_kv(stage0 + A_STAGE, ktile(1));
    CP_COMMIT();

    float O[16][4];
#pragma unroll
    for (int i = 0; i < 16; i++)
#pragma unroll
        for (int j = 0; j < 4; j++) O[i][j] = 0.f;
    float m_run[2] = { -1e30f, -1e30f };
    float l_run[2] = { 0.f, 0.f };
    const float scale2 = 0.08838834764831845f * 1.4426950408889634f;

    for (int kt = 0; kt < NT; ++kt) {
        if (kt == NT - 1) { CP_WAIT0(); } else { CP_WAIT1(); }
        __syncthreads();

        const uint32_t st = stage0 + (kt & 1) * A_STAGE;
        const uint32_t sKh = st, sKl = st + A_KTILE;
        const uint32_t sVh = st + 2 * A_KTILE, sVl = st + 3 * A_KTILE;

        float sacc[8][4];
#pragma unroll
        for (int i = 0; i < 8; i++)
#pragma unroll
            for (int j = 0; j < 4; j++) sacc[i][j] = 0.f;

#pragma unroll
        for (int ks = 0; ks < 8; ++ks) {
            const uint32_t kb = ks * 32;
            uint32_t aH[4], aL[4];
            const uint32_t aro = (warp * 16 + (lane & 15)) * A_PITCHB
                                 + ((lane >> 4) * 16) + kb;
            LDMATRIX_X4(aH[0], aH[1], aH[2], aH[3], sQh + aro);
            LDMATRIX_X4(aL[0], aL[1], aL[2], aL[3], sQl + aro);
            uint32_t bH[4][4], bL[4][4];
#pragma unroll
            for (int nb = 0; nb < 4; ++nb) {
                const uint32_t bro = (nb * 16 + (lane & 7) + ((lane >> 4) << 3))
                                     * A_PITCHB + (((lane >> 3) & 1) * 16) + kb;
                LDMATRIX_X4(bH[nb][0], bH[nb][1], bH[nb][2], bH[nb][3], sKh + bro);
                LDMATRIX_X4(bL[nb][0], bL[nb][1], bL[nb][2], bL[nb][3], sKl + bro);
            }
#pragma unroll
            for (int nb = 0; nb < 4; ++nb)
#pragma unroll
                for (int half = 0; half < 2; ++half) {
                    uint32_t b2[2] = { bH[nb][half * 2], bH[nb][half * 2 + 1] };
                    MMA_BF16(sacc[nb * 2 + half], aH, b2);
                }
#pragma unroll
            for (int nb = 0; nb < 4; ++nb)
#pragma unroll
                for (int half = 0; half < 2; ++half) {
                    uint32_t b2[2] = { bL[nb][half * 2], bL[nb][half * 2 + 1] };
                    MMA_BF16(sacc[nb * 2 + half], aH, b2);
                }
#pragma unroll
            for (int nb = 0; nb < 4; ++nb)
#pragma unroll
                for (int half = 0; half < 2; ++half) {
                    uint32_t b2[2] = { bH[nb][half * 2], bH[nb][half * 2 + 1] };
                    MMA_BF16(sacc[nb * 2 + half], aL, b2);
                }
        }

        float mt0 = -1e30f, mt1 = -1e30f;
#pragma unroll
        for (int f = 0; f < 8; ++f) {
            sacc[f][0] *= scale2; sacc[f][1] *= scale2;
            sacc[f][2] *= scale2; sacc[f][3] *= scale2;
            mt0 = fmaxf(mt0, fmaxf(sacc[f][0], sacc[f][1]));
            mt1 = fmaxf(mt1, fmaxf(sacc[f][2], sacc[f][3]));
        }
        mt0 = fmaxf(mt0, __shfl_xor_sync(0xffffffffu, mt0, 1));
        mt0 = fmaxf(mt0, __shfl_xor_sync(0xffffffffu, mt0, 2));
        mt1 = fmaxf(mt1, __shfl_xor_sync(0xffffffffu, mt1, 1));
        mt1 = fmaxf(mt1, __shfl_xor_sync(0xffffffffu, mt1, 2));
        const float mn0 = fmaxf(m_run[0], mt0), mn1 = fmaxf(m_run[1], mt1);
        const float al0 = fast_exp2(m_run[0] - mn0), al1 = fast_exp2(m_run[1] - mn1);
        m_run[0] = mn0; m_run[1] = mn1;

        float ls0 = 0.f, ls1 = 0.f;
#pragma unroll
        for (int f = 0; f < 8; ++f) {
            sacc[f][0] = fast_exp2(sacc[f][0] - mn0);
            sacc[f][1] = fast_exp2(sacc[f][1] - mn0);
            sacc[f][2] = fast_exp2(sacc[f][2] - mn1);
            sacc[f][3] = fast_exp2(sacc[f][3] - mn1);
            ls0 += sacc[f][0] + sacc[f][1];
            ls1 += sacc[f][2] + sacc[f][3];
        }
        ls0 += __shfl_xor_sync(0xffffffffu, ls0, 1);
        ls0 += __shfl_xor_sync(0xffffffffu, ls0, 2);
        ls1 += __shfl_xor_sync(0xffffffffu, ls1, 1);
        ls1 += __shfl_xor_sync(0xffffffffu, ls1, 2);
        l_run[0] = l_run[0] * al0 + ls0;
        l_run[1] = l_run[1] * al1 + ls1;

#pragma unroll
        for (int i = 0; i < 16; i++) {
            O[i][0] *= al0; O[i][1] *= al0;
            O[i][2] *= al1; O[i][3] *= al1;
        }

        uint32_t pH[4][4], pL[4][4];
#pragma unroll
        for (int j = 0; j < 4; ++j) {
            split2(sacc[2 * j][0],     sacc[2 * j][1],     pH[j][0], pL[j][0]);
            split2(sacc[2 * j][2],     sacc[2 * j][3],     pH[j][1], pL[j][1]);
            split2(sacc[2 * j + 1][0], sacc[2 * j + 1][1], pH[j][2], pL[j][2]);
            split2(sacc[2 * j + 1][2], sacc[2 * j + 1][3], pH[j][3], pL[j][3]);
        }

#pragma unroll
        for (int ks = 0; ks < 4; ++ks) {
            const uint32_t krow = ks * 16 + (lane & 7) + (((lane >> 3) & 1) * 8);
            uint32_t bH[8][4], bL[8][4];
#pragma unroll
            for (int nb = 0; nb < 8; ++nb) {
                const uint32_t ro = krow * A_PITCHB + nb * 32 + ((lane >> 4) * 16);
                LDMATRIX_X4_T(bH[nb][0], bH[nb][1], bH[nb][2], bH[nb][3], sVh + ro);
                LDMATRIX_X4_T(bL[nb][0], bL[nb][1], bL[nb][2], bL[nb][3], sVl + ro);
            }
#pragma unroll
            for (int nb = 0; nb < 8; ++nb)
#pragma unroll
                for (int half = 0; half < 2; ++half) {
                    uint32_t b2[2] = { bH[nb][half * 2], bH[nb][half * 2 + 1] };
                    MMA_BF16(O[nb * 2 + half], pH[ks], b2);
                }
#pragma unroll
            for (int nb = 0; nb < 8; ++nb)
#pragma unroll
                for (int half = 0; half < 2; ++half) {
                    uint32_t b2[2] = { bL[nb][half * 2], bL[nb][half * 2 + 1] };
                    MMA_BF16(O[nb * 2 + half], pH[ks], b2);
                }
#pragma unroll
            for (int nb = 0; nb < 8; ++nb)
#pragma unroll
                for (int half = 0; half < 2; ++half) {
                    uint32_t b2[2] = { bH[nb][half * 2], bH[nb][half * 2 + 1] };
                    MMA_BF16(O[nb * 2 + half], pL[ks], b2);
                }
        }

        __syncthreads();
        if (kt + 2 < NT) {
            load_kv(stage0 + (kt & 1) * A_STAGE, ktile(kt + 2));
            CP_COMMIT();
        }
    }

    // ---- epilogue: fp32 out [s][DIM] (tf32 frag prepass consumes it) ----
    const float inv0 = 1.f / l_run[0], inv1 = 1.f / l_run[1];
    const int s0 = qb * 128 + warp * 16 + (lane >> 2);
#pragma unroll
    for (int nf = 0; nf < 16; ++nf) {
        const int col = h * DH + nf * 8 + (lane & 3) * 2;
        *reinterpret_cast<float2*>(out + (size_t)s0 * DIM + col) =
            make_float2(O[nf][0] * inv0, O[nf][1] * inv0);
        *reinterpret_cast<float2*>(out + (size_t)(s0 + 8) * DIM + col) =
            make_float2(O[nf][2] * inv1, O[nf][3] * inv1);
    }
}

// ---------------------------------------------------------------------------
// Launch
// ---------------------------------------------------------------------------
extern "C" void kernel_launch(void* const* d_in, const int* in_sizes, int n_in,
                              void* d_out, int out_size)
{
    const float* hidden = (const float*)d_in[0];
    const float* cos_t  = (const float*)d_in[1];
    const float* sin_t  = (const float*)d_in[2];
    const float* w_qkv  = (const float*)d_in[3];
    const float* b_qkv  = (const float*)d_in[4];
    const float* w_qn   = (const float*)d_in[5];
    const float* w_kn   = (const float*)d_in[6];
    const float* w_out  = (const float*)d_in[7];
    const float* b_out  = (const float*)d_in[8];
    float* out = (float*)d_out;

    float *qkv, *At, *Wqt, *Wot;
    __nv_bfloat16 *Qh, *Ql, *Kh, *Kl, *Vh, *Vl;
    cudaGetSymbolAddress((void**)&qkv, g_qkv);
    cudaGetSymbolAddress((void**)&At, g_At);
    cudaGetSymbolAddress((void**)&Wqt, g_Wqkv_t);
    cudaGetSymbolAddress((void**)&Wot, g_Wout_t);
    cudaGetSymbolAddress((void**)&Qh, g_Qh);
    cudaGetSymbolAddress((void**)&Ql, g_Ql);
    cudaGetSymbolAddress((void**)&Kh, g_Kh);
    cudaGetSymbolAddress((void**)&Kl, g_Kl);
    cudaGetSymbolAddress((void**)&Vh, g_Vh);
    cudaGetSymbolAddress((void**)&Vl, g_Vl);

    cudaFuncSetAttribute(gemm_tf32, cudaFuncAttributeMaxDynamicSharedMemorySize,
                         GEMM_SMEM);
    cudaFuncSetAttribute(attn_tc, cudaFuncAttributeMaxDynamicSharedMemorySize,
                         ATTN_SMEM);

    // Prepass: tf32 frag-major conversions
    w_to_tf32_frag<<<dim3(N3 / 8 / 8, DIM / 16), 256>>>(w_qkv, Wqt, DIM, N3);
    w_to_tf32_frag<<<dim3(DIM / 8 / 8, DIM / 16), 256>>>(w_out, Wot, DIM, DIM);
    a_to_tf32_frag<<<(S_LEN / 16) * (DIM / 8) * 32 / 256, 256>>>(hidden, At, DIM);

    // 1) QKV = X @ Wqkv + b (tf32 tensor cores)
    gemm_tf32<<<dim3(S_LEN / 128, N3 / 128), 256, GEMM_SMEM>>>(
        At, Wqt, b_qkv, qkv, N3);

    // 2) RMSNorm + RoPE + split q,k,v to bf16 hi/lo
    rmsnorm_rope_split<<<S_LEN, 256>>>(qkv, cos_t, sin_t, w_qn, w_kn,
                                       Qh, Ql, Kh, Kl, Vh, Vl);

    // 3) Tensor-core flash attention (fp32 out into g_qkv's first S*DIM)
    attn_tc<<<dim3(S_LEN / 128, NH), 256, ATTN_SMEM>>>(Qh, Ql, Kh, Kl, Vh, Vl, qkv);

    // 4) convert attn out to tf32 frags, then out-proj (tf32 tensor cores)
    a_to_tf32_frag<<<(S_LEN / 16) * (DIM / 8) * 32 / 256, 256>>>(qkv, At, DIM);
    gemm_tf32<<<dim3(S_LEN / 128, DIM / 128), 256, GEMM_SMEM>>>(
        At, Wot, b_out, out, DIM);
}

// round 16
// speedup vs baseline: 1.4378x; 1.0037x over previous
#include <cuda_runtime.h>
#include <cuda_bf16.h>
#include <cstdint>

// Shapes (fixed by the problem)
#define S_LEN 2048
#define DIM   5120
#define NH    40
#define DH    128
#define N3    15360   // 3*DIM

// ---------------------------------------------------------------------------
// Scratch (device globals)
// ---------------------------------------------------------------------------
__device__ float g_qkv[(size_t)S_LEN * N3];          // QKV GEMM out
__device__ float g_At[(size_t)S_LEN * DIM];          // tf32 frag-major activations
__device__ float g_Wqkv_t[(size_t)N3 * DIM];         // tf32 frag-major w_qkv^T
__device__ float g_Wout_t[(size_t)DIM * DIM];        // tf32 frag-major w_out^T
// bf16 hi/lo q/k/v for tensor-core attention, [s][DIM]
__device__ __nv_bfloat16 g_Qh[(size_t)S_LEN * DIM];
__device__ __nv_bfloat16 g_Ql[(size_t)S_LEN * DIM];
__device__ __nv_bfloat16 g_Kh[(size_t)S_LEN * DIM];
__device__ __nv_bfloat16 g_Kl[(size_t)S_LEN * DIM];
__device__ __nv_bfloat16 g_Vh[(size_t)S_LEN * DIM];
__device__ __nv_bfloat16 g_Vl[(size_t)S_LEN * DIM];

// ---------------------------------------------------------------------------
// Baseline-PTX helpers
// ---------------------------------------------------------------------------
__device__ __forceinline__ uint32_t smem_u32(const void* p) {
    uint32_t a;
    asm("{ .reg .u64 t; cvta.to.shared.u64 t, %1; cvt.u32.u64 %0, t; }"
        : "=r"(a) : "l"(p));
    return a;
}

#define CP_ASYNC16(dst, src) \
    asm volatile("cp.async.cg.shared.global [%0], [%1], 16;" \
        :: "r"(dst), "l"(src) : "memory")
#define CP_COMMIT() asm volatile("cp.async.commit_group;" ::: "memory")
#define CP_WAIT0()  asm volatile("cp.async.wait_group 0;" ::: "memory")
#define CP_WAIT1()  asm volatile("cp.async.wait_group 1;" ::: "memory")

#define LDMATRIX_X4(r0, r1, r2, r3, addr) \
    asm volatile("ldmatrix.sync.aligned.m8n8.x4.shared.b16 {%0,%1,%2,%3}, [%4];" \
        : "=r"(r0), "=r"(r1), "=r"(r2), "=r"(r3) : "r"(addr))
#define LDMATRIX_X4_T(r0, r1, r2, r3, addr) \
    asm volatile("ldmatrix.sync.aligned.m8n8.x4.trans.shared.b16 {%0,%1,%2,%3}, [%4];" \
        : "=r"(r0), "=r"(r1), "=r"(r2), "=r"(r3) : "r"(addr))

#define LDS128U(r0, r1, r2, r3, addr) \
    asm volatile("ld.shared.v4.b32 {%0,%1,%2,%3}, [%4];" \
        : "=r"(r0), "=r"(r1), "=r"(r2), "=r"(r3) : "r"(addr))

#define MMA_BF16(d, a, b) \
    asm volatile( \
        "mma.sync.aligned.m16n8k16.row.col.f32.bf16.bf16.f32 " \
        "{%0,%1,%2,%3}, {%4,%5,%6,%7}, {%8,%9}, {%0,%1,%2,%3};" \
        : "+f"((d)[0]), "+f"((d)[1]), "+f"((d)[2]), "+f"((d)[3]) \
        : "r"((a)[0]), "r"((a)[1]), "r"((a)[2]), "r"((a)[3]), \
          "r"((b)[0]), "r"((b)[1]))

#define MMA_TF32(d, a, b0v, b1v) \
    asm volatile( \
        "mma.sync.aligned.m16n8k8.row.col.f32.tf32.tf32.f32 " \
        "{%0,%1,%2,%3}, {%4,%5,%6,%7}, {%8,%9}, {%0,%1,%2,%3};" \
        : "+f"((d)[0]), "+f"((d)[1]), "+f"((d)[2]), "+f"((d)[3]) \
        : "r"((a)[0]), "r"((a)[1]), "r"((a)[2]), "r"((a)[3]), \
          "r"(b0v), "r"(b1v))

__device__ __forceinline__ uint32_t f2tf32(float x) {
    uint32_t y;
    asm("cvt.rna.tf32.f32 %0, %1;" : "=r"(y) : "f"(x));
    return y;
}

__device__ __forceinline__ float fast_exp2(float x) {
    float y;
    asm("ex2.approx.f32 %0, %1;" : "=f"(y) : "f"(x));
    return y;
}

// fp32 pair -> packed bf16x2 hi + residual lo (attention path)
__device__ __forceinline__ void split2(float a, float b, uint32_t& hi, uint32_t& lo) {
    __nv_bfloat16 ha = __float2bfloat16(a), hb = __float2bfloat16(b);
    __nv_bfloat162 h2(ha, hb);
    __nv_bfloat162 l2(__float2bfloat16(a - __bfloat162float(ha)),
                      __float2bfloat16(b - __bfloat162float(hb)));
    hi = *reinterpret_cast<uint32_t*>(&h2);
    lo = *reinterpret_cast<uint32_t*>(&l2);
}

// ---------------------------------------------------------------------------
// Prepass A: X [M][K] fp32 -> frag-major tf32 blocks (m16 x k8, 512 B each).
// Block id = m_blk*(K/8) + k_blk. Lane l regs = (row+{0,8}, col+{0,4}),
// row = l>>2, col = l&3 (mma m16n8k8 A-fragment order).
// ---------------------------------------------------------------------------
__global__ __launch_bounds__(256)
void a_to_tf32_frag(const float* __restrict__ X, float* __restrict__ At, int K)
{
    const size_t gid = (size_t)blockIdx.x * 256 + threadIdx.x;
    const int lane = (int)(gid & 31);
    const size_t blk = gid >> 5;
    const int kb = (int)(blk % (K / 8));
    const int mb = (int)(blk / (K / 8));
    const int row = mb * 16 + (lane >> 2);
    const int col = kb * 8 + (lane & 3);
    uint4 o;
    o.x = f2tf32(X[(size_t)row * K + col]);
    o.y = f2tf32(X[(size_t)(row + 8) * K + col]);
    o.z = f2tf32(X[(size_t)row * K + col + 4]);
    o.w = f2tf32(X[(size_t)(row + 8) * K + col + 4]);
    reinterpret_cast<uint4*>(At)[gid] = o;
}

// ---------------------------------------------------------------------------
// Prepass B: W [K][N] fp32 -> frag-major tf32 blocks (n8 x k16, 512 B each).
// ---------------------------------------------------------------------------
__global__ __launch_bounds__(256)
void w_to_tf32_frag(const float* __restrict__ W, float* __restrict__ Bt,
                    int K, int N)
{
    const int lane = threadIdx.x & 31;
    const int sub  = threadIdx.x >> 5;
    const int nb   = blockIdx.x * 8 + sub;
    const int kb   = blockIdx.y;
    const int n = nb * 8 + (lane >> 2);
    const int k = kb * 16 + (lane & 3);
    uint4 o;
    o.x = f2tf32(W[(size_t)k * N + n]);
    o.y = f2tf32(W[(size_t)(k + 4) * N + n]);
    o.z = f2tf32(W[(size_t)(k + 8) * N + n]);
    o.w = f2tf32(W[(size_t)(k + 12) * N + n]);
    const size_t blk = (size_t)nb * (K / 16) + kb;
    reinterpret_cast<uint4*>(Bt)[blk * 32 + lane] = o;
}

// ---------------------------------------------------------------------------
// tf32 GEMM: C[M,N] = A@B + bias. Frag-major operands, CTA 128x128, 8 warps,
// BK=32. ROUND 11: 3-stage cp.async pipeline (loads issued 2 chunks ahead,
// DRAM latency fully covered). 96 KB smem, still 2 CTAs/SM.
// ---------------------------------------------------------------------------
#define BK        32
#define A_STG     16384
#define B_STG     16384
#define STAGE_B   (A_STG + B_STG)          // 32768
#define NSTAGE    3
#define GEMM_SMEM (NSTAGE * STAGE_B)       // 98304

__global__ __launch_bounds__(256, 2)
void gemm_tf32(const float* __restrict__ At, const float* __restrict__ Bt,
               const float* __restrict__ bias, float* __restrict__ C, int N)
{
    constexpr int K = DIM;
    constexpr int NCHUNK = K / BK;   // 160
    const int KB8 = K / 8, KB16 = K / 16;

    extern __shared__ char dsm[];
    const uint32_t sbase = smem_u32(dsm);

    const int tid = threadIdx.x;
    const int wid = tid >> 5, lane = tid & 31;
    const int warp_m = wid & 3;
    const int warp_n = wid >> 2;
    const int mb0 = blockIdx.x * 8;
    const int nb0 = blockIdx.y * 16;

    const int coff = ((blockIdx.y * gridDim.x + blockIdx.x) & 1) * (NCHUNK / 2);
    auto chunk_koff = [&](int c) {
        int cc = c + coff;
        if (cc >= NCHUNK) cc -= NCHUNK;
        return cc * BK;
    };

    auto load_stage = [&](int stage, int koff) {
        const uint32_t sb = sbase + stage * STAGE_B;
        const int kb8_0 = koff / 8, kb16_0 = koff / 16;
#pragma unroll
        for (int i = 0; i < 4; ++i) {
            const int g = tid + i * 256;
            const int ab = g >> 5, l = g & 31;
            const int mb = ab >> 2, kb = ab & 3;
            const float* src = At + ((size_t)(mb0 + mb) * KB8 + kb8_0 + kb) * 128 + l * 4;
            CP_ASYNC16(sb + ab * 512 + l * 16, src);
        }
#pragma unroll
        for (int i = 0; i < 4; ++i) {
            const int g = tid + i * 256;
            const int bb = g >> 5, l = g & 31;
            const int nb = bb >> 1, kb = bb & 1;
            const float* src = Bt + ((size_t)(nb0 + nb) * KB16 + kb16_0 + kb) * 128 + l * 4;
            CP_ASYNC16(sb + A_STG + bb * 512 + l * 16, src);
        }
    };

    float acc[2][8][4];
#pragma unroll
    for (int i = 0; i < 2; i++)
#pragma unroll
        for (int j = 0; j < 8; j++)
#pragma unroll
            for (int v = 0; v < 4; v++) acc[i][j][v] = 0.f;

    load_stage(0, chunk_koff(0));
    CP_COMMIT();
    load_stage(1, chunk_koff(1));
    CP_COMMIT();

    int stage = 0;
    for (int c = 0; c < NCHUNK; ++c) {
        CP_WAIT1();              // chunk c's load complete (c+1 may be in flight)
        __syncthreads();         // all warps done with the stage being reloaded
        if (c + 2 < NCHUNK) {
            int st2 = stage + 2; if (st2 >= NSTAGE) st2 -= NSTAGE;
            load_stage(st2, chunk_koff(c + 2));
            CP_COMMIT();
        }

        const uint32_t sb = sbase + stage * STAGE_B;
        const uint32_t sA = sb, sB = sb + A_STG;

#pragma unroll
        for (int q = 0; q < 2; ++q) {
            uint32_t bf[8][4];
#pragma unroll
            for (int nf = 0; nf < 8; ++nf) {
                const uint32_t ro = (uint32_t)(((warp_n * 8 + nf) * 2 + q) * 512 + lane * 16);
                LDS128U(bf[nf][0], bf[nf][1], bf[nf][2], bf[nf][3], sB + ro);
            }
#pragma unroll
            for (int mf = 0; mf < 2; ++mf) {
                uint32_t af[2][4];
#pragma unroll
                for (int s = 0; s < 2; ++s) {
                    const uint32_t ro = (uint32_t)(((warp_m * 2 + mf) * 4 + q * 2 + s) * 512
                                                   + lane * 16);
                    LDS128U(af[s][0], af[s][1], af[s][2], af[s][3], sA + ro);
                }
#pragma unroll
                for (int nf = 0; nf < 8; ++nf)
                    MMA_TF32(acc[mf][nf], af[0], bf[nf][0], bf[nf][1]);
#pragma unroll
                for (int nf = 0; nf < 8; ++nf)
                    MMA_TF32(acc[mf][nf], af[1], bf[nf][2], bf[nf][3]);
            }
        }
        if (++stage == NSTAGE) stage = 0;
    }

#pragma unroll
    for (int mf = 0; mf < 2; ++mf) {
        const int r0 = (mb0 + warp_m * 2 + mf) * 16 + (lane >> 2);
#pragma unroll
        for (int nf = 0; nf < 8; ++nf) {
            const int col = (nb0 + warp_n * 8 + nf) * 8 + (lane & 3) * 2;
            const float b0 = bias[col], b1 = bias[col + 1];
            float* p0 = C + (size_t)r0 * N + col;
            float* p1 = C + (size_t)(r0 + 8) * N + col;
            *reinterpret_cast<float2*>(p0) =
                make_float2(acc[mf][nf][0] + b0, acc[mf][nf][1] + b1);
            *reinterpret_cast<float2*>(p1) =
                make_float2(acc[mf][nf][2] + b0, acc[mf][nf][3] + b1);
        }
    }
}

// ---------------------------------------------------------------------------
// Fused RMSNorm(q,k) + RoPE + hi/lo split of q,k,v -> bf16 buffers [s][DIM].
// ---------------------------------------------------------------------------
__global__ __launch_bounds__(256)
void rmsnorm_rope_split(const float* __restrict__ qkv,
                        const float* __restrict__ cos_t,
                        const float* __restrict__ sin_t,
                        const float* __restrict__ wq,
                        const float* __restrict__ wk,
                        __nv_bfloat16* __restrict__ Qh, __nv_bfloat16* __restrict__ Ql,
                        __nv_bfloat16* __restrict__ Kh, __nv_bfloat16* __restrict__ Kl,
                        __nv_bfloat16* __restrict__ Vh, __nv_bfloat16* __restrict__ Vl)
{
    const int s = blockIdx.x;
    const float* q = qkv + (size_t)s * N3;
    const float* k = q + DIM;
    const float* v = k + DIM;

    float sq = 0.f, sk = 0.f;
    for (int i = threadIdx.x; i < DIM; i += blockDim.x) {
        float a = q[i]; sq += a * a;
        float b = k[i]; sk += b * b;
    }
#pragma unroll
    for (int o = 16; o; o >>= 1) {
        sq += __shfl_xor_sync(0xffffffffu, sq, o);
        sk += __shfl_xor_sync(0xffffffffu, sk, o);
    }
    __shared__ float red[2][32];
    const int wid = threadIdx.x >> 5, lid = threadIdx.x & 31;
    if (lid == 0) { red[0][wid] = sq; red[1][wid] = sk; }
    __syncthreads();
    if (threadIdx.x == 0) {
        float a = 0.f, b = 0.f;
        for (int i = 0; i < 8; i++) { a += red[0][i]; b += red[1][i]; }
        red[0][0] = a; red[1][0] = b;
    }
    __syncthreads();
    const float rq = rsqrtf(red[0][0] / (float)DIM + 1e-6f);
    const float rk = rsqrtf(red[1][0] / (float)DIM + 1e-6f);

    const size_t ob = (size_t)s * DIM;
    for (int p = threadIdx.x; p < DIM / 2; p += blockDim.x) {
        const int e = 2 * p, o = 2 * p + 1;
        const int ih = p & 63;
        const float ce = cos_t[s * DH + 2 * ih];
        const float so = sin_t[s * DH + 2 * ih + 1];

        float qe = q[e] * rq * wq[e], qo = q[o] * rq * wq[o];
        float ke = k[e] * rk * wk[e], ko = k[o] * rk * wk[o];
        uint32_t hi, lo;
        split2(qe * ce - qo * so, qe * so + qo * ce, hi, lo);
        *reinterpret_cast<uint32_t*>(Qh + ob + e) = hi;
        *reinterpret_cast<uint32_t*>(Ql + ob + e) = lo;
        split2(ke * ce - ko * so, ke * so + ko * ce, hi, lo);
        *reinterpret_cast<uint32_t*>(Kh + ob + e) = hi;
        *reinterpret_cast<uint32_t*>(Kl + ob + e) = lo;
        split2(v[e], v[o], hi, lo);
        *reinterpret_cast<uint32_t*>(Vh + ob + e) = hi;
        *reinterpret_cast<uint32_t*>(Vl + ob + e) = lo;
    }
}

// ---------------------------------------------------------------------------
// Tensor-core flash attention (mma.sync bf16 hi/lo, exp2-domain softmax).
// ROUND 11: epilogue writes tf32 A-fragments into g_At directly (out-proj
// operand), removing the fp32 round-trip + separate conversion launch.
// ---------------------------------------------------------------------------
#define A_BK     64
#define A_PITCHB 272
#define A_QBYTES (128 * A_PITCHB)
#define A_KTILE  (A_BK * A_PITCHB)
#define A_STAGE  (4 * A_KTILE)
#define ATTN_SMEM (2 * A_QBYTES + 2 * A_STAGE)

__global__ __launch_bounds__(256)
void attn_tc(const __nv_bfloat16* __restrict__ Qh, const __nv_bfloat16* __restrict__ Ql,
             const __nv_bfloat16* __restrict__ Kh, const __nv_bfloat16* __restrict__ Kl,
             const __nv_bfloat16* __restrict__ Vh, const __nv_bfloat16* __restrict__ Vl,
             float* __restrict__ At)
{
    extern __shared__ char dsm[];
    const uint32_t base = smem_u32(dsm);
    const uint32_t sQh = base, sQl = base + A_QBYTES;
    const uint32_t stage0 = base + 2 * A_QBYTES;

    const int qb = blockIdx.x;
    const int h  = blockIdx.y;
    const int tid = threadIdx.x;
    const int warp = tid >> 5, lane = tid & 31;

    constexpr int NT = S_LEN / A_BK;              // 32
    const int toff = ((qb + h) & 3) * (NT / 4);

    const __nv_bfloat16* kvsrc[4] = { Kh, Kl, Vh, Vl };

    {
        const size_t qoff = (size_t)(qb * 128) * DIM + h * DH;
#pragma unroll
        for (int g = 0; g < 8; ++g) {
            const int idx = tid + g * 256;
            const int row = idx >> 4, c = idx & 15;
            const size_t so = qoff + (size_t)row * DIM + c * 8;
            CP_ASYNC16(sQh + row * A_PITCHB + c * 16, Qh + so);
            CP_ASYNC16(sQl + row * A_PITCHB + c * 16, Ql + so);
        }
    }
    auto ktile = [&](int i) {
        int t = i + toff;
        return t >= NT ? t - NT : t;
    };
    auto load_kv = [&](uint32_t st, int kt) {
        const size_t koff = (size_t)(kt * A_BK) * DIM + h * DH;
#pragma unroll
        for (int g = 0; g < 16; ++g) {
            const int t = g >> 2;
            const int idx = tid + (g & 3) * 256;
            const int row = idx >> 4, c = idx & 15;
            CP_ASYNC16(st + t * A_KTILE + row * A_PITCHB + c * 16,
                       kvsrc[t] + koff + (size_t)row * DIM + c * 8);
        }
    };

    load_kv(stage0, ktile(0));
    CP_COMMIT();
    load_kv(stage0 + A_STAGE, ktile(1));
    CP_COMMIT();

    float O[16][4];
#pragma unroll
    for (int i = 0; i < 16; i++)
#pragma unroll
        for (int j = 0; j < 4; j++) O[i][j] = 0.f;
    float m_run[2] = { -1e30f, -1e30f };
    float l_run[2] = { 0.f, 0.f };
    const float scale2 = 0.08838834764831845f * 1.4426950408889634f;

    for (int kt = 0; kt < NT; ++kt) {
        if (kt == NT - 1) { CP_WAIT0(); } else { CP_WAIT1(); }
        __syncthreads();

        const uint32_t st = stage0 + (kt & 1) * A_STAGE;
        const uint32_t sKh = st, sKl = st + A_KTILE;
        const uint32_t sVh = st + 2 * A_KTILE, sVl = st + 3 * A_KTILE;

        float sacc[8][4];
#pragma unroll
        for (int i = 0; i < 8; i++)
#pragma unroll
            for (int j = 0; j < 4; j++) sacc[i][j] = 0.f;

#pragma unroll
        for (int ks = 0; ks < 8; ++ks) {
            const uint32_t kb = ks * 32;
            uint32_t aH[4], aL[4];
            const uint32_t aro = (warp * 16 + (lane & 15)) * A_PITCHB
                                 + ((lane >> 4) * 16) + kb;
            LDMATRIX_X4(aH[0], aH[1], aH[2], aH[3], sQh + aro);
            LDMATRIX_X4(aL[0], aL[1], aL[2], aL[3], sQl + aro);
            uint32_t bH[4][4], bL[4][4];
#pragma unroll
            for (int nb = 0; nb < 4; ++nb) {
                const uint32_t bro = (nb * 16 + (lane & 7) + ((lane >> 4) << 3))
                                     * A_PITCHB + (((lane >> 3) & 1) * 16) + kb;
                LDMATRIX_X4(bH[nb][0], bH[nb][1], bH[nb][2], bH[nb][3], sKh + bro);
                LDMATRIX_X4(bL[nb][0], bL[nb][1], bL[nb][2], bL[nb][3], sKl + bro);
            }
#pragma unroll
            for (int nb = 0; nb < 4; ++nb)
#pragma unroll
                for (int half = 0; half < 2; ++half) {
                    uint32_t b2[2] = { bH[nb][half * 2], bH[nb][half * 2 + 1] };
                    MMA_BF16(sacc[nb * 2 + half], aH, b2);
                }
#pragma unroll
            for (int nb = 0; nb < 4; ++nb)
#pragma unroll
                for (int half = 0; half < 2; ++half) {
                    uint32_t b2[2] = { bL[nb][half * 2], bL[nb][half * 2 + 1] };
                    MMA_BF16(sacc[nb * 2 + half], aH, b2);
                }
#pragma unroll
            for (int nb = 0; nb < 4; ++nb)
#pragma unroll
                for (int half = 0; half < 2; ++half) {
                    uint32_t b2[2] = { bH[nb][half * 2], bH[nb][half * 2 + 1] };
                    MMA_BF16(sacc[nb * 2 + half], aL, b2);
                }
        }

        float mt0 = -1e30f, mt1 = -1e30f;
#pragma unroll
        for (int f = 0; f < 8; ++f) {
            sacc[f][0] *= scale2; sacc[f][1] *= scale2;
            sacc[f][2] *= scale2; sacc[f][3] *= scale2;
            mt0 = fmaxf(mt0, fmaxf(sacc[f][0], sacc[f][1]));
            mt1 = fmaxf(mt1, fmaxf(sacc[f][2], sacc[f][3]));
        }
        mt0 = fmaxf(mt0, __shfl_xor_sync(0xffffffffu, mt0, 1));
        mt0 = fmaxf(mt0, __shfl_xor_sync(0xffffffffu, mt0, 2));
        mt1 = fmaxf(mt1, __shfl_xor_sync(0xffffffffu, mt1, 1));
        mt1 = fmaxf(mt1, __shfl_xor_sync(0xffffffffu, mt1, 2));
        const float mn0 = fmaxf(m_run[0], mt0), mn1 = fmaxf(m_run[1], mt1);
        const float al0 = fast_exp2(m_run[0] - mn0), al1 = fast_exp2(m_run[1] - mn1);
        m_run[0] = mn0; m_run[1] = mn1;

        float ls0 = 0.f, ls1 = 0.f;
#pragma unroll
        for (int f = 0; f < 8; ++f) {
            sacc[f][0] = fast_exp2(sacc[f][0] - mn0);
            sacc[f][1] = fast_exp2(sacc[f][1] - mn0);
            sacc[f][2] = fast_exp2(sacc[f][2] - mn1);
            sacc[f][3] = fast_exp2(sacc[f][3] - mn1);
            ls0 += sacc[f][0] + sacc[f][1];
            ls1 += sacc[f][2] + sacc[f][3];
        }
        ls0 += __shfl_xor_sync(0xffffffffu, ls0, 1);
        ls0 += __shfl_xor_sync(0xffffffffu, ls0, 2);
        ls1 += __shfl_xor_sync(0xffffffffu, ls1, 1);
        ls1 += __shfl_xor_sync(0xffffffffu, ls1, 2);
        l_run[0] = l_run[0] * al0 + ls0;
        l_run[1] = l_run[1] * al1 + ls1;

#pragma unroll
        for (int i = 0; i < 16; i++) {
            O[i][0] *= al0; O[i][1] *= al0;
            O[i][2] *= al1; O[i][3] *= al1;
        }

        uint32_t pH[4][4], pL[4][4];
#pragma unroll
        for (int j = 0; j < 4; ++j) {
            split2(sacc[2 * j][0],     sacc[2 * j][1],     pH[j][0], pL[j][0]);
            split2(sacc[2 * j][2],     sacc[2 * j][3],     pH[j][1], pL[j][1]);
            split2(sacc[2 * j + 1][0], sacc[2 * j + 1][1], pH[j][2], pL[j][2]);
            split2(sacc[2 * j + 1][2], sacc[2 * j + 1][3], pH[j][3], pL[j][3]);
        }

#pragma unroll
        for (int ks = 0; ks < 4; ++ks) {
            const uint32_t krow = ks * 16 + (lane & 7) + (((lane >> 3) & 1) * 8);
            uint32_t bH[8][4], bL[8][4];
#pragma unroll
            for (int nb = 0; nb < 8; ++nb) {
                const uint32_t ro = krow * A_PITCHB + nb * 32 + ((lane >> 4) * 16);
                LDMATRIX_X4_T(bH[nb][0], bH[nb][1], bH[nb][2], bH[nb][3], sVh + ro);
                LDMATRIX_X4_T(bL[nb][0], bL[nb][1], bL[nb][2], bL[nb][3], sVl + ro);
            }
#pragma unroll
            for (int nb = 0; nb < 8; ++nb)
#pragma unroll
                for (int half = 0; half < 2; ++half) {
                    uint32_t b2[2] = { bH[nb][half * 2], bH[nb][half * 2 + 1] };
                    MMA_BF16(O[nb * 2 + half], pH[ks], b2);
                }
#pragma unroll
            for (int nb = 0; nb < 8; ++nb)
#pragma unroll
                for (int half = 0; half < 2; ++half) {
                    uint32_t b2[2] = { bL[nb][half * 2], bL[nb][half * 2 + 1] };
                    MMA_BF16(O[nb * 2 + half], pH[ks], b2);
                }
#pragma unroll
            for (int nb = 0; nb < 8; ++nb)
#pragma unroll
                for (int half = 0; half < 2; ++half) {
                    uint32_t b2[2] = { bH[nb][half * 2], bH[nb][half * 2 + 1] };
                    MMA_BF16(O[nb * 2 + half], pL[ks], b2);
                }
        }

        __syncthreads();
        if (kt + 2 < NT) {
            load_kv(stage0 + (kt & 1) * A_STAGE, ktile(kt + 2));
            CP_COMMIT();
        }
    }

    // ---- epilogue: write tf32 A-fragments into At (out-proj operand) ----
    // At block layout: blk = mb*(DIM/8) + kb_g, 128 floats/block;
    //   float index = lane'*4 + reg,  lane' = rr*4 + (c&3),
    //   reg = (row>=8 ? 1 : 0) + (c>=4 ? 2 : 0).
    // This warp's rows: rr = lane>>2 (regRow 0) and rr+8 (regRow 1),
    // cols per nf-block: c = 2j, 2j+1 with j = lane&3.
    const float inv0 = 1.f / l_run[0], inv1 = 1.f / l_run[1];
    const int mb = qb * 8 + warp;              // m16-block index
    const int rr = lane >> 2;
    const int j  = lane & 3;
#pragma unroll
    for (int nf = 0; nf < 16; ++nf) {
        const int kb_g = h * 16 + nf;          // global k8-block
        float* blkp = At + ((size_t)mb * (DIM / 8) + kb_g) * 128;
#pragma unroll
        for (int cc2 = 0; cc2 < 2; ++cc2) {
            const int c = 2 * j + cc2;
            const int lp = rr * 4 + (c & 3);
            const int regc = (c >> 2) * 2;
            const float v0 = O[nf][cc2] * inv0;        // row rr
            const float v1 = O[nf][2 + cc2] * inv1;    // row rr+8
            blkp[lp * 4 + regc]     = __uint_as_float(f2tf32(v0));
            blkp[lp * 4 + regc + 1] = __uint_as_float(f2tf32(v1));
        }
    }
}

// ---------------------------------------------------------------------------
// Launch
// ---------------------------------------------------------------------------
extern "C" void kernel_launch(void* const* d_in, const int* in_sizes, int n_in,
                              void* d_out, int out_size)
{
    const float* hidden = (const float*)d_in[0];
    const float* cos_t  = (const float*)d_in[1];
    const float* sin_t  = (const float*)d_in[2];
    const float* w_qkv  = (const float*)d_in[3];
    const float* b_qkv  = (const float*)d_in[4];
    const float* w_qn   = (const float*)d_in[5];
    const float* w_kn   = (const float*)d_in[6];
    const float* w_out  = (const float*)d_in[7];
    const float* b_out  = (const float*)d_in[8];
    float* out = (float*)d_out;

    float *qkv, *At, *Wqt, *Wot;
    __nv_bfloat16 *Qh, *Ql, *Kh, *Kl, *Vh, *Vl;
    cudaGetSymbolAddress((void**)&qkv, g_qkv);
    cudaGetSymbolAddress((void**)&At, g_At);
    cudaGetSymbolAddress((void**)&Wqt, g_Wqkv_t);
    cudaGetSymbolAddress((void**)&Wot, g_Wout_t);
    cudaGetSymbolAddress((void**)&Qh, g_Qh);
    cudaGetSymbolAddress((void**)&Ql, g_Ql);
    cudaGetSymbolAddress((void**)&Kh, g_Kh);
    cudaGetSymbolAddress((void**)&Kl, g_Kl);
    cudaGetSymbolAddress((void**)&Vh, g_Vh);
    cudaGetSymbolAddress((void**)&Vl, g_Vl);

    cudaFuncSetAttribute(gemm_tf32, cudaFuncAttributeMaxDynamicSharedMemorySize,
                         GEMM_SMEM);
    cudaFuncSetAttribute(attn_tc, cudaFuncAttributeMaxDynamicSharedMemorySize,
                         ATTN_SMEM);

    // Prepass: tf32 frag-major conversions
    w_to_tf32_frag<<<dim3(N3 / 8 / 8, DIM / 16), 256>>>(w_qkv, Wqt, DIM, N3);
    w_to_tf32_frag<<<dim3(DIM / 8 / 8, DIM / 16), 256>>>(w_out, Wot, DIM, DIM);
    a_to_tf32_frag<<<(S_LEN / 16) * (DIM / 8) * 32 / 256, 256>>>(hidden, At, DIM);

    // 1) QKV = X @ Wqkv + b (tf32 tensor cores, 3-stage pipeline)
    gemm_tf32<<<dim3(S_LEN / 128, N3 / 128), 256, GEMM_SMEM>>>(
        At, Wqt, b_qkv, qkv, N3);

    // 2) RMSNorm + RoPE + split q,k,v to bf16 hi/lo
    rmsnorm_rope_split<<<S_LEN, 256>>>(qkv, cos_t, sin_t, w_qn, w_kn,
                                       Qh, Ql, Kh, Kl, Vh, Vl);

    // 3) Tensor-core flash attention -> tf32 frags directly into At
    attn_tc<<<dim3(S_LEN / 128, NH), 256, ATTN_SMEM>>>(Qh, Ql, Kh, Kl, Vh, Vl, At);

    // 4) out = attn_out @ Wout + b (tf32 tensor cores)
    gemm_tf32<<<dim3(S_LEN / 128, DIM / 128), 256, GEMM_SMEM>>>(
        At, Wot, b_out, out, DIM);
}